// round 3
// baseline (speedup 1.0000x reference)
#include <cuda_runtime.h>
#include <math.h>

#define B_      2
#define L_      1024
#define DM      768
#define DI      1536
#define DS      16
#define DTR     48
#define VOCAB_  50264
#define ROWS    (B_*L_)   // 2048

// ---------------- scratch (static device memory; no allocation) ----------------
__device__ float g_x[ROWS*DM];
__device__ float g_xn[ROWS*DM];
__device__ float g_xr[ROWS*2*DI];
__device__ float g_u[ROWS*DI];
__device__ float g_xdbl[ROWS*80];
__device__ float g_delta[ROWS*DI];
__device__ float g_y[ROWS*DI];

// ---------------- embedding gather ----------------
__global__ void embed_kernel(const int* __restrict__ ids,
                             const float* __restrict__ emb,
                             float* __restrict__ x)
{
    int idx = blockIdx.x*blockDim.x + threadIdx.x;
    if (idx >= ROWS*DM) return;
    int row = idx / DM, c = idx % DM;
    x[idx] = emb[(size_t)ids[row]*DM + c];
}

// ---------------- rmsnorm (one block per row of 768) ----------------
__global__ void rmsnorm_kernel(const float* __restrict__ x,
                               const float* __restrict__ w,
                               float* __restrict__ out)
{
    __shared__ float red[8];
    int row = blockIdx.x;
    const float* xr = x + (size_t)row*DM;
    float s = 0.f;
    for (int c = threadIdx.x; c < DM; c += 256) { float v = xr[c]; s += v*v; }
    #pragma unroll
    for (int o = 16; o; o >>= 1) s += __shfl_xor_sync(0xffffffffu, s, o);
    if ((threadIdx.x & 31) == 0) red[threadIdx.x >> 5] = s;
    __syncthreads();
    if (threadIdx.x < 8) {
        s = red[threadIdx.x];
        #pragma unroll
        for (int o = 4; o; o >>= 1) s += __shfl_xor_sync(0xffu, s, o);
        if (threadIdx.x == 0) red[0] = s;
    }
    __syncthreads();
    float scale = rsqrtf(red[0] / (float)DM + 1e-5f);
    for (int c = threadIdx.x; c < DM; c += 256)
        out[(size_t)row*DM + c] = xr[c] * scale * w[c];
}

// ---------------- generic tiled SGEMM:  C[M,N] = A[M,K] @ W[N,K]^T ----------------
// M assumed multiple of 128. N guarded. K multiple of 8.
// ep: 0=none, 1=softplus(acc+bias[n]), 2=acc+resid[m*N+n]
__global__ void __launch_bounds__(256, 2) gemm_nt(
    const float* __restrict__ A, int lda,
    const float* __restrict__ W,
    float* __restrict__ C,
    int N, int K, int ep,
    const float* __restrict__ bias,
    const float* __restrict__ resid)
{
    __shared__ float As[8][128];
    __shared__ float Bs[8][128];
    const int tid = threadIdx.x;
    const int tx = tid & 15;
    const int ty = tid >> 4;
    const int m0 = blockIdx.y * 128;
    const int n0 = blockIdx.x * 128;
    const int lr = tid >> 1;          // 0..127
    const int lc = (tid & 1) * 4;     // 0 or 4

    float acc[8][8];
    #pragma unroll
    for (int i = 0; i < 8; i++)
        #pragma unroll
        for (int j = 0; j < 8; j++) acc[i][j] = 0.f;

    const float* Aptr = A + (size_t)(m0 + lr)*lda + lc;
    const bool wvalid = (n0 + lr) < N;
    const float* Wptr = W + (size_t)(wvalid ? (n0 + lr) : 0)*K + lc;

    for (int k0 = 0; k0 < K; k0 += 8) {
        float4 av = *(const float4*)(Aptr + k0);
        float4 bv = make_float4(0.f, 0.f, 0.f, 0.f);
        if (wvalid) bv = *(const float4*)(Wptr + k0);
        __syncthreads();
        As[lc+0][lr] = av.x; As[lc+1][lr] = av.y; As[lc+2][lr] = av.z; As[lc+3][lr] = av.w;
        Bs[lc+0][lr] = bv.x; Bs[lc+1][lr] = bv.y; Bs[lc+2][lr] = bv.z; Bs[lc+3][lr] = bv.w;
        __syncthreads();
        #pragma unroll
        for (int k = 0; k < 8; k++) {
            float4 a0 = *(const float4*)&As[k][ty*8];
            float4 a1 = *(const float4*)&As[k][ty*8+4];
            float4 b0 = *(const float4*)&Bs[k][tx*8];
            float4 b1 = *(const float4*)&Bs[k][tx*8+4];
            float ar[8] = {a0.x,a0.y,a0.z,a0.w,a1.x,a1.y,a1.z,a1.w};
            float br[8] = {b0.x,b0.y,b0.z,b0.w,b1.x,b1.y,b1.z,b1.w};
            #pragma unroll
            for (int i = 0; i < 8; i++)
                #pragma unroll
                for (int j = 0; j < 8; j++)
                    acc[i][j] = fmaf(ar[i], br[j], acc[i][j]);
        }
    }

    #pragma unroll
    for (int i = 0; i < 8; i++) {
        int m = m0 + ty*8 + i;
        #pragma unroll
        for (int j = 0; j < 8; j++) {
            int n = n0 + tx*8 + j;
            if (n < N) {
                float v = acc[i][j];
                if (ep == 1) {
                    v += bias[n];
                    v = (v > 20.f) ? v : log1pf(expf(v));
                } else if (ep == 2) {
                    v += resid[(size_t)m*N + n];
                }
                C[(size_t)m*N + n] = v;
            }
        }
    }
}

// ---------------- depthwise causal conv (k=4) + bias + silu ----------------
__global__ void conv_silu_kernel(const float* __restrict__ xr,
                                 const float* __restrict__ cw,
                                 const float* __restrict__ cb,
                                 float* __restrict__ u)
{
    int idx = blockIdx.x*blockDim.x + threadIdx.x;
    if (idx >= ROWS*DI) return;
    int d = idx % DI;
    int row = idx / DI;          // b*L + t
    int t = row % L_;
    float acc = cb[d];
    #pragma unroll
    for (int j = 0; j < 4; ++j) {
        int tt = t - 3 + j;
        if (tt >= 0)
            acc = fmaf(cw[d*4 + j], xr[(size_t)(row - 3 + j)*(2*DI) + d], acc);
    }
    u[idx] = acc / (1.f + __expf(-acc));
}

// ---------------- selective scan: 16 lanes per (b,d) channel ----------------
__global__ void scan_kernel(const float* __restrict__ delta,  // [ROWS, DI]
                            const float* __restrict__ u,      // [ROWS, DI]
                            const float* __restrict__ xdbl,   // [ROWS, 80]
                            const float* __restrict__ alog,   // [DI, 16]
                            float* __restrict__ y)            // [ROWS, DI]
{
    int gid = blockIdx.x*blockDim.x + threadIdx.x;
    int ch = gid >> 4;
    if (ch >= B_*DI) return;
    int n = gid & 15;
    int b = ch / DI, d = ch % DI;
    float An = -__expf(alog[d*DS + n]);
    float state = 0.f;
    const float* drow = delta + (size_t)b*L_*DI + d;
    const float* urow = u     + (size_t)b*L_*DI + d;
    const float* xrow = xdbl  + (size_t)b*L_*80 + DTR + n;
    float* yrow = y + (size_t)b*L_*DI + d;
    for (int t = 0; t < L_; ++t) {
        float dt = drow[(size_t)t*DI];
        float uu = urow[(size_t)t*DI];
        float Bn = xrow[(size_t)t*80];
        float Cn = xrow[(size_t)t*80 + DS];
        float dA = __expf(dt * An);
        state = fmaf(dA, state, dt * Bn * uu);
        float p = state * Cn;
        p += __shfl_xor_sync(0xffffffffu, p, 8);
        p += __shfl_xor_sync(0xffffffffu, p, 4);
        p += __shfl_xor_sync(0xffffffffu, p, 2);
        p += __shfl_xor_sync(0xffffffffu, p, 1);
        if (n == 0) yrow[(size_t)t*DI] = p;
    }
}

// ---------------- y = (y + u*D) * silu(res) ----------------
__global__ void gate_kernel(float* __restrict__ y,
                            const float* __restrict__ u,
                            const float* __restrict__ Dv,
                            const float* __restrict__ xr)
{
    int idx = blockIdx.x*blockDim.x + threadIdx.x;
    if (idx >= ROWS*DI) return;
    int d = idx % DI;
    int row = idx / DI;
    float r = xr[(size_t)row*(2*DI) + DI + d];
    float g = r / (1.f + __expf(-r));
    y[idx] = (y[idx] + u[idx]*Dv[d]) * g;
}

// ---------------- launcher ----------------
extern "C" void kernel_launch(void* const* d_in, const int* in_sizes, int n_in,
                              void* d_out, int out_size)
{
    (void)in_sizes; (void)n_in; (void)out_size;
    const int*   ids  = (const int*)d_in[0];
    const float* emb  = (const float*)d_in[2];
    const float* inw  = (const float*)d_in[3];
    const float* cw   = (const float*)d_in[4];
    const float* cb   = (const float*)d_in[5];
    const float* xpw  = (const float*)d_in[6];
    const float* dtw  = (const float*)d_in[7];
    const float* dtb  = (const float*)d_in[8];
    const float* alog = (const float*)d_in[9];
    const float* Dv   = (const float*)d_in[10];
    const float* outw = (const float*)d_in[11];
    const float* nw   = (const float*)d_in[12];
    const float* nfw  = (const float*)d_in[13];
    float* out = (float*)d_out;

    float *x, *xn, *xr, *u, *xdbl, *delta, *y;
    cudaGetSymbolAddress((void**)&x,     g_x);
    cudaGetSymbolAddress((void**)&xn,    g_xn);
    cudaGetSymbolAddress((void**)&xr,    g_xr);
    cudaGetSymbolAddress((void**)&u,     g_u);
    cudaGetSymbolAddress((void**)&xdbl,  g_xdbl);
    cudaGetSymbolAddress((void**)&delta, g_delta);
    cudaGetSymbolAddress((void**)&y,     g_y);

    embed_kernel<<<(ROWS*DM + 255)/256, 256>>>(ids, emb, x);

    for (int l = 0; l < 2; ++l) {
        rmsnorm_kernel<<<ROWS, 256>>>(x, nw + l*DM, xn);
        // x_and_res = xn @ in_proj^T : [2048, 3072]
        gemm_nt<<<dim3((2*DI + 127)/128, ROWS/128), 256>>>(
            xn, DM, inw + (size_t)l*2*DI*DM, xr, 2*DI, DM, 0, nullptr, nullptr);
        // depthwise conv + silu -> u
        conv_silu_kernel<<<(ROWS*DI + 255)/256, 256>>>(xr, cw + l*DI*4, cb + l*DI, u);
        // x_dbl = u @ x_proj^T : [2048, 80]
        gemm_nt<<<dim3(1, ROWS/128), 256>>>(
            u, DI, xpw + (size_t)l*80*DI, xdbl, 80, DI, 0, nullptr, nullptr);
        // delta = softplus(x_dbl[:, :48] @ dt_proj^T + dt_b) : [2048, 1536]
        gemm_nt<<<dim3(DI/128, ROWS/128), 256>>>(
            xdbl, 80, dtw + (size_t)l*DI*DTR, delta, DI, DTR, 1, dtb + l*DI, nullptr);
        // selective scan -> y
        scan_kernel<<<(B_*DI*16)/256, 256>>>(delta, u, xdbl, alog + l*DI*DS, y);
        // gate: y = (y + u*D) * silu(res)
        gate_kernel<<<(ROWS*DI + 255)/256, 256>>>(y, u, Dv + l*DI, xr);
        // x = y @ out_proj^T + x (residual)
        gemm_nt<<<dim3(DM/128, ROWS/128), 256>>>(
            y, DI, outw + (size_t)l*DM*DI, x, DM, DI, 2, nullptr, x);
    }

    rmsnorm_kernel<<<ROWS, 256>>>(x, nfw, xn);
    // logits = xn @ embedding^T : [2048, 50264]
    gemm_nt<<<dim3((VOCAB_ + 127)/128, ROWS/128), 256>>>(
        xn, DM, emb, out, VOCAB_, DM, 0, nullptr, nullptr);
}

// round 4
// speedup vs baseline: 1.1841x; 1.1841x over previous
#include <cuda_runtime.h>
#include <math.h>

#define B_      2
#define L_      1024
#define DM      768
#define DI      1536
#define DS      16
#define DTR     48
#define VOCAB_  50264
#define ROWS    (B_*L_)   // 2048

// ---------------- scratch (static device memory; no allocation) ----------------
__device__ float g_x[ROWS*DM];
__device__ float g_xn[ROWS*DM];
__device__ float g_xr[ROWS*2*DI];
__device__ float g_u[ROWS*DI];
__device__ float g_xdbl[ROWS*80];
__device__ float g_delta[ROWS*DI];
__device__ float g_y[ROWS*DI];

// ---------------- embedding gather ----------------
__global__ void embed_kernel(const int* __restrict__ ids,
                             const float* __restrict__ emb,
                             float* __restrict__ x)
{
    int idx = blockIdx.x*blockDim.x + threadIdx.x;
    if (idx >= ROWS*DM) return;
    int row = idx / DM, c = idx % DM;
    x[idx] = emb[(size_t)ids[row]*DM + c];
}

// ---------------- rmsnorm (one block per row of 768) ----------------
__global__ void rmsnorm_kernel(const float* __restrict__ x,
                               const float* __restrict__ w,
                               float* __restrict__ out)
{
    __shared__ float red[8];
    int row = blockIdx.x;
    const float* xr = x + (size_t)row*DM;
    float s = 0.f;
    for (int c = threadIdx.x; c < DM; c += 256) { float v = xr[c]; s += v*v; }
    #pragma unroll
    for (int o = 16; o; o >>= 1) s += __shfl_xor_sync(0xffffffffu, s, o);
    if ((threadIdx.x & 31) == 0) red[threadIdx.x >> 5] = s;
    __syncthreads();
    if (threadIdx.x < 8) {
        s = red[threadIdx.x];
        #pragma unroll
        for (int o = 4; o; o >>= 1) s += __shfl_xor_sync(0xffu, s, o);
        if (threadIdx.x == 0) red[0] = s;
    }
    __syncthreads();
    float scale = rsqrtf(red[0] / (float)DM + 1e-5f);
    for (int c = threadIdx.x; c < DM; c += 256)
        out[(size_t)row*DM + c] = xr[c] * scale * w[c];
}

// ---------------- tf32 helpers ----------------
__device__ __forceinline__ unsigned f2tf32(float x)
{
    unsigned r;
    asm("cvt.rna.tf32.f32 %0, %1;" : "=r"(r) : "f"(x));
    return r;
}

__device__ __forceinline__ void mma_tf32(float* c, const unsigned* a, const unsigned* b)
{
    asm volatile(
        "mma.sync.aligned.m16n8k8.row.col.f32.tf32.tf32.f32 "
        "{%0,%1,%2,%3}, {%4,%5,%6,%7}, {%8,%9}, {%0,%1,%2,%3};"
        : "+f"(c[0]), "+f"(c[1]), "+f"(c[2]), "+f"(c[3])
        : "r"(a[0]), "r"(a[1]), "r"(a[2]), "r"(a[3]), "r"(b[0]), "r"(b[1]));
}

// ---------------- split-tf32 tensor GEMM:  C[M,N] = A[M,K] @ W[N,K]^T ----------------
// 128x128 block tile, 8 warps (4 in M x 2 in N), warp tile 32x64, k-step 8.
// A and W are split into tf32 hi + lo; acc += hi*hi + lo*hi + hi*lo  (near-fp32 precision).
// M multiple of 128, K multiple of 8, N guarded. ep: 0=none, 2=acc+resid[m*N+n].
__global__ void __launch_bounds__(256) gemm_tf32_nt(
    const float* __restrict__ A, int lda,
    const float* __restrict__ W,
    float* __restrict__ C,
    int N, int K, int ep,
    const float* __restrict__ resid)
{
    // padded stride 20: conflict-free fragment reads (m*20+k distinct banks)
    __shared__ float As[128][20];   // cols 0..7 = hi, 8..15 = lo
    __shared__ float Bs[128][20];

    const int tid  = threadIdx.x;
    const int lane = tid & 31;
    const int warp = tid >> 5;
    const int wm   = warp & 3;        // 4 warps along M (32 rows each)
    const int wn   = warp >> 2;       // 2 warps along N (64 cols each)
    const int gid  = lane >> 2;       // 0..7
    const int tig  = lane & 3;        // 0..3

    const int m0 = blockIdx.y * 128;
    const int n0 = blockIdx.x * 128;

    const int lr = tid >> 1;          // 0..127 (tile row loaded by this thread)
    const int lc = (tid & 1) * 4;     // 0 or 4

    float acc[2][8][4];
    #pragma unroll
    for (int i = 0; i < 2; i++)
        #pragma unroll
        for (int j = 0; j < 8; j++)
            #pragma unroll
            for (int v = 0; v < 4; v++) acc[i][j][v] = 0.f;

    const float* Aptr = A + (size_t)(m0 + lr)*lda + lc;
    const bool wvalid = (n0 + lr) < N;
    const float* Wptr = W + (size_t)(wvalid ? (n0 + lr) : 0)*K + lc;

    for (int k0 = 0; k0 < K; k0 += 8) {
        float4 av = *(const float4*)(Aptr + k0);
        float4 bv = make_float4(0.f, 0.f, 0.f, 0.f);
        if (wvalid) bv = *(const float4*)(Wptr + k0);
        __syncthreads();
        {
            float a4[4] = {av.x, av.y, av.z, av.w};
            float b4[4] = {bv.x, bv.y, bv.z, bv.w};
            #pragma unroll
            for (int j = 0; j < 4; j++) {
                unsigned h = f2tf32(a4[j]);
                float lo = a4[j] - __uint_as_float(h);
                As[lr][lc + j]     = __uint_as_float(h);
                As[lr][lc + j + 8] = __uint_as_float(f2tf32(lo));
                unsigned hb = f2tf32(b4[j]);
                float lob = b4[j] - __uint_as_float(hb);
                Bs[lr][lc + j]     = __uint_as_float(hb);
                Bs[lr][lc + j + 8] = __uint_as_float(f2tf32(lob));
            }
        }
        __syncthreads();

        // load fragments
        unsigned ahi[2][4], alo[2][4];
        #pragma unroll
        for (int mi = 0; mi < 2; mi++) {
            int r0 = wm*32 + mi*16 + gid;
            ahi[mi][0] = __float_as_uint(As[r0    ][tig    ]);
            ahi[mi][1] = __float_as_uint(As[r0 + 8][tig    ]);
            ahi[mi][2] = __float_as_uint(As[r0    ][tig + 4]);
            ahi[mi][3] = __float_as_uint(As[r0 + 8][tig + 4]);
            alo[mi][0] = __float_as_uint(As[r0    ][tig + 8]);
            alo[mi][1] = __float_as_uint(As[r0 + 8][tig + 8]);
            alo[mi][2] = __float_as_uint(As[r0    ][tig +12]);
            alo[mi][3] = __float_as_uint(As[r0 + 8][tig +12]);
        }
        unsigned bhi[8][2], blo[8][2];
        #pragma unroll
        for (int ni = 0; ni < 8; ni++) {
            int c0 = wn*64 + ni*8 + gid;
            bhi[ni][0] = __float_as_uint(Bs[c0][tig    ]);
            bhi[ni][1] = __float_as_uint(Bs[c0][tig + 4]);
            blo[ni][0] = __float_as_uint(Bs[c0][tig + 8]);
            blo[ni][1] = __float_as_uint(Bs[c0][tig +12]);
        }

        #pragma unroll
        for (int mi = 0; mi < 2; mi++)
            #pragma unroll
            for (int ni = 0; ni < 8; ni++) {
                mma_tf32(acc[mi][ni], ahi[mi], bhi[ni]);
                mma_tf32(acc[mi][ni], alo[mi], bhi[ni]);
                mma_tf32(acc[mi][ni], ahi[mi], blo[ni]);
            }
    }

    // epilogue
    #pragma unroll
    for (int mi = 0; mi < 2; mi++) {
        #pragma unroll
        for (int ni = 0; ni < 8; ni++) {
            int r = m0 + wm*32 + mi*16 + gid;
            int c = n0 + wn*64 + ni*8 + tig*2;
            #pragma unroll
            for (int v = 0; v < 4; v++) {
                int m = r + (v >> 1)*8;
                int n = c + (v & 1);
                if (n < N) {
                    float val = acc[mi][ni][v];
                    if (ep == 2) val += resid[(size_t)m*N + n];
                    C[(size_t)m*N + n] = val;
                }
            }
        }
    }
}

// ---------------- generic tiled SGEMM (small shapes):  C[M,N] = A[M,K] @ W[N,K]^T ----------------
// ep: 0=none, 1=softplus(acc+bias[n])
__global__ void __launch_bounds__(256, 2) gemm_nt(
    const float* __restrict__ A, int lda,
    const float* __restrict__ W,
    float* __restrict__ C,
    int N, int K, int ep,
    const float* __restrict__ bias)
{
    __shared__ float As[8][128];
    __shared__ float Bs[8][128];
    const int tid = threadIdx.x;
    const int tx = tid & 15;
    const int ty = tid >> 4;
    const int m0 = blockIdx.y * 128;
    const int n0 = blockIdx.x * 128;
    const int lr = tid >> 1;
    const int lc = (tid & 1) * 4;

    float acc[8][8];
    #pragma unroll
    for (int i = 0; i < 8; i++)
        #pragma unroll
        for (int j = 0; j < 8; j++) acc[i][j] = 0.f;

    const float* Aptr = A + (size_t)(m0 + lr)*lda + lc;
    const bool wvalid = (n0 + lr) < N;
    const float* Wptr = W + (size_t)(wvalid ? (n0 + lr) : 0)*K + lc;

    for (int k0 = 0; k0 < K; k0 += 8) {
        float4 av = *(const float4*)(Aptr + k0);
        float4 bv = make_float4(0.f, 0.f, 0.f, 0.f);
        if (wvalid) bv = *(const float4*)(Wptr + k0);
        __syncthreads();
        As[lc+0][lr] = av.x; As[lc+1][lr] = av.y; As[lc+2][lr] = av.z; As[lc+3][lr] = av.w;
        Bs[lc+0][lr] = bv.x; Bs[lc+1][lr] = bv.y; Bs[lc+2][lr] = bv.z; Bs[lc+3][lr] = bv.w;
        __syncthreads();
        #pragma unroll
        for (int k = 0; k < 8; k++) {
            float4 a0 = *(const float4*)&As[k][ty*8];
            float4 a1 = *(const float4*)&As[k][ty*8+4];
            float4 b0 = *(const float4*)&Bs[k][tx*8];
            float4 b1 = *(const float4*)&Bs[k][tx*8+4];
            float ar[8] = {a0.x,a0.y,a0.z,a0.w,a1.x,a1.y,a1.z,a1.w};
            float br[8] = {b0.x,b0.y,b0.z,b0.w,b1.x,b1.y,b1.z,b1.w};
            #pragma unroll
            for (int i = 0; i < 8; i++)
                #pragma unroll
                for (int j = 0; j < 8; j++)
                    acc[i][j] = fmaf(ar[i], br[j], acc[i][j]);
        }
    }

    #pragma unroll
    for (int i = 0; i < 8; i++) {
        int m = m0 + ty*8 + i;
        #pragma unroll
        for (int j = 0; j < 8; j++) {
            int n = n0 + tx*8 + j;
            if (n < N) {
                float v = acc[i][j];
                if (ep == 1) {
                    v += bias[n];
                    v = (v > 20.f) ? v : log1pf(expf(v));
                }
                C[(size_t)m*N + n] = v;
            }
        }
    }
}

// ---------------- depthwise causal conv (k=4) + bias + silu ----------------
__global__ void conv_silu_kernel(const float* __restrict__ xr,
                                 const float* __restrict__ cw,
                                 const float* __restrict__ cb,
                                 float* __restrict__ u)
{
    int idx = blockIdx.x*blockDim.x + threadIdx.x;
    if (idx >= ROWS*DI) return;
    int d = idx % DI;
    int row = idx / DI;          // b*L + t
    int t = row % L_;
    float acc = cb[d];
    #pragma unroll
    for (int j = 0; j < 4; ++j) {
        int tt = t - 3 + j;
        if (tt >= 0)
            acc = fmaf(cw[d*4 + j], xr[(size_t)(row - 3 + j)*(2*DI) + d], acc);
    }
    u[idx] = acc / (1.f + __expf(-acc));
}

// ---------------- selective scan: 16 lanes per (b,d) channel ----------------
__global__ void scan_kernel(const float* __restrict__ delta,
                            const float* __restrict__ u,
                            const float* __restrict__ xdbl,
                            const float* __restrict__ alog,
                            float* __restrict__ y)
{
    int gid = blockIdx.x*blockDim.x + threadIdx.x;
    int ch = gid >> 4;
    if (ch >= B_*DI) return;
    int n = gid & 15;
    int b = ch / DI, d = ch % DI;
    float An = -__expf(alog[d*DS + n]);
    float state = 0.f;
    const float* drow = delta + (size_t)b*L_*DI + d;
    const float* urow = u     + (size_t)b*L_*DI + d;
    const float* xrow = xdbl  + (size_t)b*L_*80 + DTR + n;
    float* yrow = y + (size_t)b*L_*DI + d;
    for (int t = 0; t < L_; ++t) {
        float dt = drow[(size_t)t*DI];
        float uu = urow[(size_t)t*DI];
        float Bn = xrow[(size_t)t*80];
        float Cn = xrow[(size_t)t*80 + DS];
        float dA = __expf(dt * An);
        state = fmaf(dA, state, dt * Bn * uu);
        float p = state * Cn;
        p += __shfl_xor_sync(0xffffffffu, p, 8);
        p += __shfl_xor_sync(0xffffffffu, p, 4);
        p += __shfl_xor_sync(0xffffffffu, p, 2);
        p += __shfl_xor_sync(0xffffffffu, p, 1);
        if (n == 0) yrow[(size_t)t*DI] = p;
    }
}

// ---------------- y = (y + u*D) * silu(res) ----------------
__global__ void gate_kernel(float* __restrict__ y,
                            const float* __restrict__ u,
                            const float* __restrict__ Dv,
                            const float* __restrict__ xr)
{
    int idx = blockIdx.x*blockDim.x + threadIdx.x;
    if (idx >= ROWS*DI) return;
    int d = idx % DI;
    int row = idx / DI;
    float r = xr[(size_t)row*(2*DI) + DI + d];
    float g = r / (1.f + __expf(-r));
    y[idx] = (y[idx] + u[idx]*Dv[d]) * g;
}

// ---------------- launcher ----------------
extern "C" void kernel_launch(void* const* d_in, const int* in_sizes, int n_in,
                              void* d_out, int out_size)
{
    (void)in_sizes; (void)n_in; (void)out_size;
    const int*   ids  = (const int*)d_in[0];
    const float* emb  = (const float*)d_in[2];
    const float* inw  = (const float*)d_in[3];
    const float* cw   = (const float*)d_in[4];
    const float* cb   = (const float*)d_in[5];
    const float* xpw  = (const float*)d_in[6];
    const float* dtw  = (const float*)d_in[7];
    const float* dtb  = (const float*)d_in[8];
    const float* alog = (const float*)d_in[9];
    const float* Dv   = (const float*)d_in[10];
    const float* outw = (const float*)d_in[11];
    const float* nw   = (const float*)d_in[12];
    const float* nfw  = (const float*)d_in[13];
    float* out = (float*)d_out;

    float *x, *xn, *xr, *u, *xdbl, *delta, *y;
    cudaGetSymbolAddress((void**)&x,     g_x);
    cudaGetSymbolAddress((void**)&xn,    g_xn);
    cudaGetSymbolAddress((void**)&xr,    g_xr);
    cudaGetSymbolAddress((void**)&u,     g_u);
    cudaGetSymbolAddress((void**)&xdbl,  g_xdbl);
    cudaGetSymbolAddress((void**)&delta, g_delta);
    cudaGetSymbolAddress((void**)&y,     g_y);

    embed_kernel<<<(ROWS*DM + 255)/256, 256>>>(ids, emb, x);

    for (int l = 0; l < 2; ++l) {
        rmsnorm_kernel<<<ROWS, 256>>>(x, nw + l*DM, xn);
        // x_and_res = xn @ in_proj^T : [2048, 3072]   (tensor, split-tf32)
        gemm_tf32_nt<<<dim3((2*DI + 127)/128, ROWS/128), 256>>>(
            xn, DM, inw + (size_t)l*2*DI*DM, xr, 2*DI, DM, 0, nullptr);
        // depthwise conv + silu -> u
        conv_silu_kernel<<<(ROWS*DI + 255)/256, 256>>>(xr, cw + l*DI*4, cb + l*DI, u);
        // x_dbl = u @ x_proj^T : [2048, 80]   (small, FFMA)
        gemm_nt<<<dim3(1, ROWS/128), 256>>>(
            u, DI, xpw + (size_t)l*80*DI, xdbl, 80, DI, 0, nullptr);
        // delta = softplus(x_dbl[:, :48] @ dt_proj^T + dt_b) : [2048, 1536]  (K=48, FFMA)
        gemm_nt<<<dim3(DI/128, ROWS/128), 256>>>(
            xdbl, 80, dtw + (size_t)l*DI*DTR, delta, DI, DTR, 1, dtb + l*DI);
        // selective scan -> y
        scan_kernel<<<(B_*DI*16)/256, 256>>>(delta, u, xdbl, alog + l*DI*DS, y);
        // gate: y = (y + u*D) * silu(res)
        gate_kernel<<<(ROWS*DI + 255)/256, 256>>>(y, u, Dv + l*DI, xr);
        // x = y @ out_proj^T + x (residual)   (tensor, split-tf32)
        gemm_tf32_nt<<<dim3(DM/128, ROWS/128), 256>>>(
            y, DI, outw + (size_t)l*DM*DI, x, DM, DI, 2, x);
    }

    rmsnorm_kernel<<<ROWS, 256>>>(x, nfw, xn);
    // logits = xn @ embedding^T : [2048, 50264]   (tensor, split-tf32)
    gemm_tf32_nt<<<dim3((VOCAB_ + 127)/128, ROWS/128), 256>>>(
        xn, DM, emb, out, VOCAB_, DM, 0, nullptr);
}

// round 6
// speedup vs baseline: 2.5450x; 2.1494x over previous
#include <cuda_runtime.h>
#include <cuda_bf16.h>
#include <math.h>
#include <stdint.h>

#define B_      2
#define L_      1024
#define DM      768
#define DI      1536
#define DS      16
#define DTR     48
#define VOCAB_  50264
#define ROWS    (B_*L_)   // 2048

// ---------------- scratch (static device memory; no allocation) ----------------
__device__ float g_x[ROWS*DM];
__device__ float g_xn[ROWS*DM];
__device__ float g_xr[ROWS*2*DI];
__device__ float g_u[ROWS*DI];
__device__ float g_xdbl[ROWS*80];
__device__ float g_delta[ROWS*DI];
__device__ float g_y[ROWS*DI];
// split activation buffers (max 2048x1536)
__device__ __nv_bfloat16 g_ahi[ROWS*DI];
__device__ __nv_bfloat16 g_alo[ROWS*DI];
// split weight buffers (max = embedding 50264x768)
__device__ __nv_bfloat16 g_whi[(size_t)VOCAB_*DM];
__device__ __nv_bfloat16 g_wlo[(size_t)VOCAB_*DM];

// ================= helpers =================
__device__ __forceinline__ uint32_t smem_u32(const void* p) {
    uint32_t a;
    asm("{ .reg .u64 t; cvta.to.shared.u64 t, %1; cvt.u32.u64 %0, t; }" : "=r"(a) : "l"(p));
    return a;
}
__device__ __forceinline__ void ldsm4(uint32_t* r, uint32_t addr) {
    asm volatile("ldmatrix.sync.aligned.m8n8.x4.shared.b16 {%0,%1,%2,%3}, [%4];"
        : "=r"(r[0]), "=r"(r[1]), "=r"(r[2]), "=r"(r[3]) : "r"(addr));
}
__device__ __forceinline__ void mma_bf16(float* c, const uint32_t* a, const uint32_t* b) {
    asm volatile("mma.sync.aligned.m16n8k16.row.col.f32.bf16.bf16.f32 "
        "{%0,%1,%2,%3},{%4,%5,%6,%7},{%8,%9},{%0,%1,%2,%3};"
        : "+f"(c[0]), "+f"(c[1]), "+f"(c[2]), "+f"(c[3])
        : "r"(a[0]), "r"(a[1]), "r"(a[2]), "r"(a[3]), "r"(b[0]), "r"(b[1]));
}

// ================= split fp32 -> bf16 hi + bf16 lo =================
__global__ void split_kernel(const float* __restrict__ in,
                             __nv_bfloat16* __restrict__ hi,
                             __nv_bfloat16* __restrict__ lo,
                             int n4)
{
    int i = blockIdx.x*blockDim.x + threadIdx.x;
    if (i >= n4) return;
    float4 v = ((const float4*)in)[i];
    __nv_bfloat16 h0 = __float2bfloat16(v.x), h1 = __float2bfloat16(v.y);
    __nv_bfloat16 h2 = __float2bfloat16(v.z), h3 = __float2bfloat16(v.w);
    __nv_bfloat16 l0 = __float2bfloat16(v.x - __bfloat162float(h0));
    __nv_bfloat16 l1 = __float2bfloat16(v.y - __bfloat162float(h1));
    __nv_bfloat16 l2 = __float2bfloat16(v.z - __bfloat162float(h2));
    __nv_bfloat16 l3 = __float2bfloat16(v.w - __bfloat162float(h3));
    ushort4 ho, lq;
    ho.x = __bfloat16_as_ushort(h0); ho.y = __bfloat16_as_ushort(h1);
    ho.z = __bfloat16_as_ushort(h2); ho.w = __bfloat16_as_ushort(h3);
    lq.x = __bfloat16_as_ushort(l0); lq.y = __bfloat16_as_ushort(l1);
    lq.z = __bfloat16_as_ushort(l2); lq.w = __bfloat16_as_ushort(l3);
    ((ushort4*)hi)[i] = ho;
    ((ushort4*)lo)[i] = lq;
}

// ================= bf16 split-precision tensor GEMM =================
// C[M,N] = A[M,K] @ W[N,K]^T, A/W pre-split bf16 hi/lo.
// acc += hi*hi + lo*hi + hi*lo (fp32 accum in mma).
// Block tile 128x128, k-chunk 64, 8 warps (4M x 2N), warp tile 32x64.
// ep: 0 = none, 2 = acc + resid[m*N+n]
#define SA_HI 0
#define SA_LO 16384
#define SB_HI 32768
#define SB_LO 49152
#define SM_BYTES 65536

__global__ void __launch_bounds__(256, 2) gemm_bf16(
    const __nv_bfloat16* __restrict__ Ahi, const __nv_bfloat16* __restrict__ Alo, int K,
    const __nv_bfloat16* __restrict__ Bhi, const __nv_bfloat16* __restrict__ Blo, int N,
    float* __restrict__ C, int ep, const float* __restrict__ resid)
{
    extern __shared__ char sm[];
    const uint32_t sb = smem_u32(sm);
    const int tid = threadIdx.x, wid = tid >> 5, lane = tid & 31;
    const int wm = wid & 3, wn = wid >> 2;
    const int m0 = blockIdx.y * 128;
    const int n0 = blockIdx.x * 128;

    float acc[2][8][4];
    #pragma unroll
    for (int i = 0; i < 2; i++)
        #pragma unroll
        for (int j = 0; j < 8; j++)
            #pragma unroll
            for (int v = 0; v < 4; v++) acc[i][j][v] = 0.f;

    // gmem->smem load indices (each thread: 4 uint4 per tile)
    const int lrow = tid >> 3;          // 0..31 base row (stride 32 over 4 iters)
    const int lchk = tid & 7;           // 16B chunk within 128B row

    // ldmatrix addresses (depend on ks via chunk)
    const int arow = wm*32 + (lane & 15);            // + mi*16
    const int acbit = lane >> 4;                     // chunk low bit
    const int brow0 = wn*64 + (lane & 7) + ((lane >> 4) << 3);  // + h*32 + p*16
    const int bcbit = (lane >> 3) & 1;

    const int nk = K >> 6;
    for (int kc = 0; kc < nk; kc++) {
        const int k0 = kc << 6;
        __syncthreads();
        #pragma unroll
        for (int i = 0; i < 4; i++) {
            int r = lrow + i*32;
            size_t ga = (size_t)(m0 + r)*K + k0 + lchk*8;
            uint32_t off = (uint32_t)(r*128 + ((lchk ^ (r & 7)) << 4));
            *(uint4*)(sm + SA_HI + off) = *(const uint4*)(Ahi + ga);
            *(uint4*)(sm + SA_LO + off) = *(const uint4*)(Alo + ga);
            int n = n0 + r;
            uint4 vh = make_uint4(0,0,0,0), vl = make_uint4(0,0,0,0);
            if (n < N) {
                size_t gb = (size_t)n*K + k0 + lchk*8;
                vh = *(const uint4*)(Bhi + gb);
                vl = *(const uint4*)(Blo + gb);
            }
            *(uint4*)(sm + SB_HI + off) = vh;
            *(uint4*)(sm + SB_LO + off) = vl;
        }
        __syncthreads();

        #pragma unroll
        for (int ks = 0; ks < 4; ks++) {
            uint32_t ahi[2][4], alo[2][4];
            #pragma unroll
            for (int mi = 0; mi < 2; mi++) {
                int row = arow + mi*16;
                int chunk = ks*2 + acbit;
                uint32_t off = (uint32_t)(row*128 + ((chunk ^ (row & 7)) << 4));
                ldsm4(ahi[mi], sb + SA_HI + off);
                ldsm4(alo[mi], sb + SA_LO + off);
            }
            #pragma unroll
            for (int h = 0; h < 2; h++) {
                uint32_t bhi[2][4], blo[2][4];
                #pragma unroll
                for (int p = 0; p < 2; p++) {
                    int row = brow0 + h*32 + p*16;
                    int chunk = ks*2 + bcbit;
                    uint32_t off = (uint32_t)(row*128 + ((chunk ^ (row & 7)) << 4));
                    ldsm4(bhi[p], sb + SB_HI + off);
                    ldsm4(blo[p], sb + SB_LO + off);
                }
                #pragma unroll
                for (int mi = 0; mi < 2; mi++)
                    #pragma unroll
                    for (int p = 0; p < 2; p++)
                        #pragma unroll
                        for (int q = 0; q < 2; q++) {
                            float* a = acc[mi][h*4 + p*2 + q];
                            mma_bf16(a, ahi[mi], &bhi[p][2*q]);
                            mma_bf16(a, alo[mi], &bhi[p][2*q]);
                            mma_bf16(a, ahi[mi], &blo[p][2*q]);
                        }
            }
        }
    }

    // epilogue
    const int gid = lane >> 2, tig = lane & 3;
    #pragma unroll
    for (int mi = 0; mi < 2; mi++) {
        #pragma unroll
        for (int j = 0; j < 8; j++) {
            int m = m0 + wm*32 + mi*16 + gid;
            int n = n0 + wn*64 + j*8 + tig*2;
            if (n < N) {
                float2 v0 = make_float2(acc[mi][j][0], acc[mi][j][1]);
                float2 v1 = make_float2(acc[mi][j][2], acc[mi][j][3]);
                if (ep == 2) {
                    const float2 r0 = *(const float2*)(resid + (size_t)m*N + n);
                    const float2 r1 = *(const float2*)(resid + (size_t)(m+8)*N + n);
                    v0.x += r0.x; v0.y += r0.y;
                    v1.x += r1.x; v1.y += r1.y;
                }
                *(float2*)(C + (size_t)m*N + n) = v0;
                *(float2*)(C + (size_t)(m+8)*N + n) = v1;
            }
        }
    }
}

// ================= other kernels =================
__global__ void embed_kernel(const int* __restrict__ ids,
                             const float* __restrict__ emb,
                             float* __restrict__ x)
{
    int idx = blockIdx.x*blockDim.x + threadIdx.x;
    if (idx >= ROWS*DM) return;
    int row = idx / DM, c = idx % DM;
    x[idx] = emb[(size_t)ids[row]*DM + c];
}

__global__ void rmsnorm_kernel(const float* __restrict__ x,
                               const float* __restrict__ w,
                               float* __restrict__ out)
{
    __shared__ float red[8];
    int row = blockIdx.x;
    const float* xr = x + (size_t)row*DM;
    float s = 0.f;
    for (int c = threadIdx.x; c < DM; c += 256) { float v = xr[c]; s += v*v; }
    #pragma unroll
    for (int o = 16; o; o >>= 1) s += __shfl_xor_sync(0xffffffffu, s, o);
    if ((threadIdx.x & 31) == 0) red[threadIdx.x >> 5] = s;
    __syncthreads();
    if (threadIdx.x < 8) {
        s = red[threadIdx.x];
        #pragma unroll
        for (int o = 4; o; o >>= 1) s += __shfl_xor_sync(0xffu, s, o);
        if (threadIdx.x == 0) red[0] = s;
    }
    __syncthreads();
    float scale = rsqrtf(red[0] / (float)DM + 1e-5f);
    for (int c = threadIdx.x; c < DM; c += 256)
        out[(size_t)row*DM + c] = xr[c] * scale * w[c];
}

// small FFMA GEMM for x_proj / dt_proj.  ep: 0=none, 1=softplus(acc+bias[n])
__global__ void __launch_bounds__(256, 2) gemm_nt(
    const float* __restrict__ A, int lda,
    const float* __restrict__ W,
    float* __restrict__ C,
    int N, int K, int ep,
    const float* __restrict__ bias)
{
    __shared__ float As[8][128];
    __shared__ float Bs[8][128];
    const int tid = threadIdx.x;
    const int tx = tid & 15;
    const int ty = tid >> 4;
    const int m0 = blockIdx.y * 128;
    const int n0 = blockIdx.x * 128;
    const int lr = tid >> 1;
    const int lc = (tid & 1) * 4;

    float acc[8][8];
    #pragma unroll
    for (int i = 0; i < 8; i++)
        #pragma unroll
        for (int j = 0; j < 8; j++) acc[i][j] = 0.f;

    const float* Aptr = A + (size_t)(m0 + lr)*lda + lc;
    const bool wvalid = (n0 + lr) < N;
    const float* Wptr = W + (size_t)(wvalid ? (n0 + lr) : 0)*K + lc;

    for (int k0 = 0; k0 < K; k0 += 8) {
        float4 av = *(const float4*)(Aptr + k0);
        float4 bv = make_float4(0.f, 0.f, 0.f, 0.f);
        if (wvalid) bv = *(const float4*)(Wptr + k0);
        __syncthreads();
        As[lc+0][lr] = av.x; As[lc+1][lr] = av.y; As[lc+2][lr] = av.z; As[lc+3][lr] = av.w;
        Bs[lc+0][lr] = bv.x; Bs[lc+1][lr] = bv.y; Bs[lc+2][lr] = bv.z; Bs[lc+3][lr] = bv.w;
        __syncthreads();
        #pragma unroll
        for (int k = 0; k < 8; k++) {
            float4 a0 = *(const float4*)&As[k][ty*8];
            float4 a1 = *(const float4*)&As[k][ty*8+4];
            float4 b0 = *(const float4*)&Bs[k][tx*8];
            float4 b1 = *(const float4*)&Bs[k][tx*8+4];
            float ar[8] = {a0.x,a0.y,a0.z,a0.w,a1.x,a1.y,a1.z,a1.w};
            float br[8] = {b0.x,b0.y,b0.z,b0.w,b1.x,b1.y,b1.z,b1.w};
            #pragma unroll
            for (int i = 0; i < 8; i++)
                #pragma unroll
                for (int j = 0; j < 8; j++)
                    acc[i][j] = fmaf(ar[i], br[j], acc[i][j]);
        }
    }

    #pragma unroll
    for (int i = 0; i < 8; i++) {
        int m = m0 + ty*8 + i;
        #pragma unroll
        for (int j = 0; j < 8; j++) {
            int n = n0 + tx*8 + j;
            if (n < N) {
                float v = acc[i][j];
                if (ep == 1) {
                    v += bias[n];
                    v = (v > 20.f) ? v : log1pf(expf(v));
                }
                C[(size_t)m*N + n] = v;
            }
        }
    }
}

__global__ void conv_silu_kernel(const float* __restrict__ xr,
                                 const float* __restrict__ cw,
                                 const float* __restrict__ cb,
                                 float* __restrict__ u)
{
    int idx = blockIdx.x*blockDim.x + threadIdx.x;
    if (idx >= ROWS*DI) return;
    int d = idx % DI;
    int row = idx / DI;
    int t = row % L_;
    float acc = cb[d];
    #pragma unroll
    for (int j = 0; j < 4; ++j) {
        int tt = t - 3 + j;
        if (tt >= 0)
            acc = fmaf(cw[d*4 + j], xr[(size_t)(row - 3 + j)*(2*DI) + d], acc);
    }
    u[idx] = acc / (1.f + __expf(-acc));
}

__global__ void scan_kernel(const float* __restrict__ delta,
                            const float* __restrict__ u,
                            const float* __restrict__ xdbl,
                            const float* __restrict__ alog,
                            float* __restrict__ y)
{
    int gid = blockIdx.x*blockDim.x + threadIdx.x;
    int ch = gid >> 4;
    if (ch >= B_*DI) return;
    int n = gid & 15;
    int b = ch / DI, d = ch % DI;
    float An = -__expf(alog[d*DS + n]);
    float state = 0.f;
    const float* drow = delta + (size_t)b*L_*DI + d;
    const float* urow = u     + (size_t)b*L_*DI + d;
    const float* xrow = xdbl  + (size_t)b*L_*80 + DTR + n;
    float* yrow = y + (size_t)b*L_*DI + d;
    for (int t = 0; t < L_; ++t) {
        float dt = drow[(size_t)t*DI];
        float uu = urow[(size_t)t*DI];
        float Bn = xrow[(size_t)t*80];
        float Cn = xrow[(size_t)t*80 + DS];
        float dA = __expf(dt * An);
        state = fmaf(dA, state, dt * Bn * uu);
        float p = state * Cn;
        p += __shfl_xor_sync(0xffffffffu, p, 8);
        p += __shfl_xor_sync(0xffffffffu, p, 4);
        p += __shfl_xor_sync(0xffffffffu, p, 2);
        p += __shfl_xor_sync(0xffffffffu, p, 1);
        if (n == 0) yrow[(size_t)t*DI] = p;
    }
}

__global__ void gate_kernel(float* __restrict__ y,
                            const float* __restrict__ u,
                            const float* __restrict__ Dv,
                            const float* __restrict__ xr)
{
    int idx = blockIdx.x*blockDim.x + threadIdx.x;
    if (idx >= ROWS*DI) return;
    int d = idx % DI;
    int row = idx / DI;
    float r = xr[(size_t)row*(2*DI) + DI + d];
    float g = r / (1.f + __expf(-r));
    y[idx] = (y[idx] + u[idx]*Dv[d]) * g;
}

// ================= launcher =================
static inline void do_split(const float* src, __nv_bfloat16* hi, __nv_bfloat16* lo, size_t n)
{
    int n4 = (int)(n >> 2);
    split_kernel<<<(n4 + 255)/256, 256>>>(src, hi, lo, n4);
}

extern "C" void kernel_launch(void* const* d_in, const int* in_sizes, int n_in,
                              void* d_out, int out_size)
{
    (void)in_sizes; (void)n_in; (void)out_size;
    const int*   ids  = (const int*)d_in[0];
    const float* emb  = (const float*)d_in[2];
    const float* inw  = (const float*)d_in[3];
    const float* cw   = (const float*)d_in[4];
    const float* cb   = (const float*)d_in[5];
    const float* xpw  = (const float*)d_in[6];
    const float* dtw  = (const float*)d_in[7];
    const float* dtb  = (const float*)d_in[8];
    const float* alog = (const float*)d_in[9];
    const float* Dv   = (const float*)d_in[10];
    const float* outw = (const float*)d_in[11];
    const float* nw   = (const float*)d_in[12];
    const float* nfw  = (const float*)d_in[13];
    float* out = (float*)d_out;

    float *x, *xn, *xr, *u, *xdbl, *delta, *y;
    __nv_bfloat16 *ahi, *alo, *whi, *wlo;
    cudaGetSymbolAddress((void**)&x,     g_x);
    cudaGetSymbolAddress((void**)&xn,    g_xn);
    cudaGetSymbolAddress((void**)&xr,    g_xr);
    cudaGetSymbolAddress((void**)&u,     g_u);
    cudaGetSymbolAddress((void**)&xdbl,  g_xdbl);
    cudaGetSymbolAddress((void**)&delta, g_delta);
    cudaGetSymbolAddress((void**)&y,     g_y);
    cudaGetSymbolAddress((void**)&ahi,   g_ahi);
    cudaGetSymbolAddress((void**)&alo,   g_alo);
    cudaGetSymbolAddress((void**)&whi,   g_whi);
    cudaGetSymbolAddress((void**)&wlo,   g_wlo);

    static bool attr_done = false;
    if (!attr_done) {
        cudaFuncSetAttribute(gemm_bf16, cudaFuncAttributeMaxDynamicSharedMemorySize, SM_BYTES);
        attr_done = true;
    }

    embed_kernel<<<(ROWS*DM + 255)/256, 256>>>(ids, emb, x);

    for (int l = 0; l < 2; ++l) {
        rmsnorm_kernel<<<ROWS, 256>>>(x, nw + l*DM, xn);
        // in_proj: [2048,768] @ [3072,768]^T -> xr [2048,3072]
        do_split(xn, ahi, alo, (size_t)ROWS*DM);
        do_split(inw + (size_t)l*2*DI*DM, whi, wlo, (size_t)2*DI*DM);
        gemm_bf16<<<dim3((2*DI + 127)/128, ROWS/128), 256, SM_BYTES>>>(
            ahi, alo, DM, whi, wlo, 2*DI, xr, 0, nullptr);
        conv_silu_kernel<<<(ROWS*DI + 255)/256, 256>>>(xr, cw + l*DI*4, cb + l*DI, u);
        gemm_nt<<<dim3(1, ROWS/128), 256>>>(
            u, DI, xpw + (size_t)l*80*DI, xdbl, 80, DI, 0, nullptr);
        gemm_nt<<<dim3(DI/128, ROWS/128), 256>>>(
            xdbl, 80, dtw + (size_t)l*DI*DTR, delta, DI, DTR, 1, dtb + l*DI);
        scan_kernel<<<(B_*DI*16)/256, 256>>>(delta, u, xdbl, alog + l*DI*DS, y);
        gate_kernel<<<(ROWS*DI + 255)/256, 256>>>(y, u, Dv + l*DI, xr);
        // out_proj: [2048,1536] @ [768,1536]^T + x -> x
        do_split(y, ahi, alo, (size_t)ROWS*DI);
        do_split(outw + (size_t)l*DM*DI, whi, wlo, (size_t)DM*DI);
        gemm_bf16<<<dim3((DM + 127)/128, ROWS/128), 256, SM_BYTES>>>(
            ahi, alo, DI, whi, wlo, DM, x, 2, x);
    }

    rmsnorm_kernel<<<ROWS, 256>>>(x, nfw, xn);
    // logits: [2048,768] @ [50264,768]^T -> out [2048,50264]
    do_split(xn, ahi, alo, (size_t)ROWS*DM);
    do_split(emb, whi, wlo, (size_t)VOCAB_*DM);
    gemm_bf16<<<dim3((VOCAB_ + 127)/128, ROWS/128), 256, SM_BYTES>>>(
        ahi, alo, DM, whi, wlo, VOCAB_, out, 0, nullptr);
}

// round 9
// speedup vs baseline: 3.1234x; 1.2273x over previous
#include <cuda_runtime.h>
#include <cuda_bf16.h>
#include <math.h>
#include <stdint.h>

#define B_      2
#define L_      1024
#define DM      768
#define DI      1536
#define DS      16
#define DTR     48
#define VOCAB_  50264
#define ROWS    (B_*L_)   // 2048

// ---------------- scratch (static device memory; no allocation) ----------------
__device__ float g_x[ROWS*DM];
__device__ float g_xn[ROWS*DM];
__device__ float g_xr[ROWS*2*DI];
__device__ float g_u[ROWS*DI];
__device__ float g_xdbl[ROWS*80];
__device__ float g_delta[ROWS*DI];
__device__ float g_y[ROWS*DI];
// split activation buffers (max 2048x1536)
__device__ __nv_bfloat16 g_ahi[ROWS*DI];
__device__ __nv_bfloat16 g_alo[ROWS*DI];
// split weight buffers (max = embedding 50264x768)
__device__ __nv_bfloat16 g_whi[(size_t)VOCAB_*DM];
__device__ __nv_bfloat16 g_wlo[(size_t)VOCAB_*DM];

// ================= helpers =================
__device__ __forceinline__ uint32_t smem_u32(const void* p) {
    uint32_t a;
    asm("{ .reg .u64 t; cvta.to.shared.u64 t, %1; cvt.u32.u64 %0, t; }" : "=r"(a) : "l"(p));
    return a;
}
__device__ __forceinline__ void ldsm4(uint32_t* r, uint32_t addr) {
    asm volatile("ldmatrix.sync.aligned.m8n8.x4.shared.b16 {%0,%1,%2,%3}, [%4];"
        : "=r"(r[0]), "=r"(r[1]), "=r"(r[2]), "=r"(r[3]) : "r"(addr));
}
__device__ __forceinline__ void mma_bf16(float* c, const uint32_t* a, const uint32_t* b) {
    asm volatile("mma.sync.aligned.m16n8k16.row.col.f32.bf16.bf16.f32 "
        "{%0,%1,%2,%3},{%4,%5,%6,%7},{%8,%9},{%0,%1,%2,%3};"
        : "+f"(c[0]), "+f"(c[1]), "+f"(c[2]), "+f"(c[3])
        : "r"(a[0]), "r"(a[1]), "r"(a[2]), "r"(a[3]), "r"(b[0]), "r"(b[1]));
}
__device__ __forceinline__ void cp16(uint32_t dst, const void* src, bool valid) {
    int sz = valid ? 16 : 0;
    asm volatile("cp.async.cg.shared.global [%0], [%1], 16, %2;"
                 :: "r"(dst), "l"(src), "r"(sz) : "memory");
}
__device__ __forceinline__ void cp_commit() {
    asm volatile("cp.async.commit_group;" ::: "memory");
}

// ================= split fp32 -> bf16 hi + bf16 lo =================
__global__ void split_kernel(const float* __restrict__ in,
                             __nv_bfloat16* __restrict__ hi,
                             __nv_bfloat16* __restrict__ lo,
                             int n4)
{
    int i = blockIdx.x*blockDim.x + threadIdx.x;
    if (i >= n4) return;
    float4 v = ((const float4*)in)[i];
    __nv_bfloat16 h0 = __float2bfloat16(v.x), h1 = __float2bfloat16(v.y);
    __nv_bfloat16 h2 = __float2bfloat16(v.z), h3 = __float2bfloat16(v.w);
    __nv_bfloat16 l0 = __float2bfloat16(v.x - __bfloat162float(h0));
    __nv_bfloat16 l1 = __float2bfloat16(v.y - __bfloat162float(h1));
    __nv_bfloat16 l2 = __float2bfloat16(v.z - __bfloat162float(h2));
    __nv_bfloat16 l3 = __float2bfloat16(v.w - __bfloat162float(h3));
    ushort4 ho, lq;
    ho.x = __bfloat16_as_ushort(h0); ho.y = __bfloat16_as_ushort(h1);
    ho.z = __bfloat16_as_ushort(h2); ho.w = __bfloat16_as_ushort(h3);
    lq.x = __bfloat16_as_ushort(l0); lq.y = __bfloat16_as_ushort(l1);
    lq.z = __bfloat16_as_ushort(l2); lq.w = __bfloat16_as_ushort(l3);
    ((ushort4*)hi)[i] = ho;
    ((ushort4*)lo)[i] = lq;
}

// ================= bf16 split-precision tensor GEMM =================
// C[M,N] = A[M,K] @ W[N,K]^T, A/W pre-split bf16 hi/lo.
// acc += hi*hi + lo*hi + hi*lo (fp32 accum in mma).
// Block tile 128x128, k-chunk 64, 8 warps (4M x 2N), warp tile 32x64.
// 2-stage cp.async double buffering.  Grid: x = M-tiles, y = N-tiles
// (M fastest -> concurrent waves share B tiles -> B stays L2-resident).
// ep: 0 = none, 2 = acc + resid[m*N+n]
#define SA_HI 0
#define SA_LO 16384
#define SB_HI 32768
#define SB_LO 49152
#define STG   65536
#define SM_BYTES (2*STG)   // 131072

__global__ void __launch_bounds__(256, 1) gemm_bf16(
    const __nv_bfloat16* __restrict__ Ahi, const __nv_bfloat16* __restrict__ Alo, int K,
    const __nv_bfloat16* __restrict__ Bhi, const __nv_bfloat16* __restrict__ Blo, int N,
    float* __restrict__ C, int ep, const float* __restrict__ resid)
{
    extern __shared__ char sm[];
    const uint32_t sb = smem_u32(sm);
    const int tid = threadIdx.x, wid = tid >> 5, lane = tid & 31;
    const int wm = wid & 3, wn = wid >> 2;
    const int m0 = blockIdx.x * 128;
    const int n0 = blockIdx.y * 128;

    float acc[2][8][4];
    #pragma unroll
    for (int i = 0; i < 2; i++)
        #pragma unroll
        for (int j = 0; j < 8; j++)
            #pragma unroll
            for (int v = 0; v < 4; v++) acc[i][j][v] = 0.f;

    // gmem->smem load indices (each thread: 4 rows x 16B per buffer)
    const int lrow = tid >> 3;          // 0..31 base row
    const int lchk = tid & 7;           // 16B chunk within 128B row

    // ldmatrix address components
    const int arow = wm*32 + (lane & 15);
    const int acbit = lane >> 4;
    const int brow0 = wn*64 + (lane & 7) + ((lane >> 4) << 3);
    const int bcbit = (lane >> 3) & 1;

    const int nk = K >> 6;

    auto issue = [&](int kc) {
        const int s = kc & 1;
        const int k0 = kc << 6;
        const uint32_t base = sb + s*STG;
        #pragma unroll
        for (int i = 0; i < 4; i++) {
            int r = lrow + i*32;
            size_t ga = (size_t)(m0 + r)*K + k0 + lchk*8;
            uint32_t off = (uint32_t)(r*128 + ((lchk ^ (r & 7)) << 4));
            cp16(base + SA_HI + off, Ahi + ga, true);
            cp16(base + SA_LO + off, Alo + ga, true);
            int n = n0 + r;
            bool v = n < N;
            size_t gb = (size_t)(v ? n : 0)*K + k0 + lchk*8;
            cp16(base + SB_HI + off, Bhi + gb, v);
            cp16(base + SB_LO + off, Blo + gb, v);
        }
        cp_commit();
    };

    issue(0);
    for (int kc = 0; kc < nk; kc++) {
        if (kc + 1 < nk) {
            issue(kc + 1);
            asm volatile("cp.async.wait_group 1;" ::: "memory");
        } else {
            asm volatile("cp.async.wait_group 0;" ::: "memory");
        }
        __syncthreads();

        const uint32_t stg = sb + (kc & 1)*STG;
        #pragma unroll
        for (int ks = 0; ks < 4; ks++) {
            uint32_t ahi[2][4], alo[2][4];
            #pragma unroll
            for (int mi = 0; mi < 2; mi++) {
                int row = arow + mi*16;
                int chunk = ks*2 + acbit;
                uint32_t off = (uint32_t)(row*128 + ((chunk ^ (row & 7)) << 4));
                ldsm4(ahi[mi], stg + SA_HI + off);
                ldsm4(alo[mi], stg + SA_LO + off);
            }
            #pragma unroll
            for (int h = 0; h < 2; h++) {
                uint32_t bhi[2][4], blo[2][4];
                #pragma unroll
                for (int p = 0; p < 2; p++) {
                    int row = brow0 + h*32 + p*16;
                    int chunk = ks*2 + bcbit;
                    uint32_t off = (uint32_t)(row*128 + ((chunk ^ (row & 7)) << 4));
                    ldsm4(bhi[p], stg + SB_HI + off);
                    ldsm4(blo[p], stg + SB_LO + off);
                }
                #pragma unroll
                for (int mi = 0; mi < 2; mi++)
                    #pragma unroll
                    for (int p = 0; p < 2; p++)
                        #pragma unroll
                        for (int q = 0; q < 2; q++) {
                            float* a = acc[mi][h*4 + p*2 + q];
                            mma_bf16(a, ahi[mi], &bhi[p][2*q]);
                            mma_bf16(a, alo[mi], &bhi[p][2*q]);
                            mma_bf16(a, ahi[mi], &blo[p][2*q]);
                        }
            }
        }
        __syncthreads();
    }

    // epilogue
    const int gid = lane >> 2, tig = lane & 3;
    #pragma unroll
    for (int mi = 0; mi < 2; mi++) {
        #pragma unroll
        for (int j = 0; j < 8; j++) {
            int m = m0 + wm*32 + mi*16 + gid;
            int n = n0 + wn*64 + j*8 + tig*2;
            if (n < N) {
                float2 v0 = make_float2(acc[mi][j][0], acc[mi][j][1]);
                float2 v1 = make_float2(acc[mi][j][2], acc[mi][j][3]);
                if (ep == 2) {
                    const float2 r0 = *(const float2*)(resid + (size_t)m*N + n);
                    const float2 r1 = *(const float2*)(resid + (size_t)(m+8)*N + n);
                    v0.x += r0.x; v0.y += r0.y;
                    v1.x += r1.x; v1.y += r1.y;
                }
                *(float2*)(C + (size_t)m*N + n) = v0;
                *(float2*)(C + (size_t)(m+8)*N + n) = v1;
            }
        }
    }
}

// ================= other kernels =================
__global__ void embed_kernel(const int* __restrict__ ids,
                             const float* __restrict__ emb,
                             float* __restrict__ x)
{
    int idx = blockIdx.x*blockDim.x + threadIdx.x;
    if (idx >= ROWS*DM) return;
    int row = idx / DM, c = idx % DM;
    x[idx] = emb[(size_t)ids[row]*DM + c];
}

__global__ void rmsnorm_kernel(const float* __restrict__ x,
                               const float* __restrict__ w,
                               float* __restrict__ out)
{
    __shared__ float red[8];
    int row = blockIdx.x;
    const float* xr = x + (size_t)row*DM;
    float s = 0.f;
    for (int c = threadIdx.x; c < DM; c += 256) { float v = xr[c]; s += v*v; }
    #pragma unroll
    for (int o = 16; o; o >>= 1) s += __shfl_xor_sync(0xffffffffu, s, o);
    if ((threadIdx.x & 31) == 0) red[threadIdx.x >> 5] = s;
    __syncthreads();
    if (threadIdx.x < 8) {
        s = red[threadIdx.x];
        #pragma unroll
        for (int o = 4; o; o >>= 1) s += __shfl_xor_sync(0xffu, s, o);
        if (threadIdx.x == 0) red[0] = s;
    }
    __syncthreads();
    float scale = rsqrtf(red[0] / (float)DM + 1e-5f);
    for (int c = threadIdx.x; c < DM; c += 256)
        out[(size_t)row*DM + c] = xr[c] * scale * w[c];
}

// small FFMA GEMM (dt_proj).  ep: 0=none, 1=softplus(acc+bias[n])
__global__ void __launch_bounds__(256, 2) gemm_nt(
    const float* __restrict__ A, int lda,
    const float* __restrict__ W,
    float* __restrict__ C,
    int N, int K, int ep,
    const float* __restrict__ bias)
{
    __shared__ float As[8][128];
    __shared__ float Bs[8][128];
    const int tid = threadIdx.x;
    const int tx = tid & 15;
    const int ty = tid >> 4;
    const int m0 = blockIdx.y * 128;
    const int n0 = blockIdx.x * 128;
    const int lr = tid >> 1;
    const int lc = (tid & 1) * 4;

    float acc[8][8];
    #pragma unroll
    for (int i = 0; i < 8; i++)
        #pragma unroll
        for (int j = 0; j < 8; j++) acc[i][j] = 0.f;

    const float* Aptr = A + (size_t)(m0 + lr)*lda + lc;
    const bool wvalid = (n0 + lr) < N;
    const float* Wptr = W + (size_t)(wvalid ? (n0 + lr) : 0)*K + lc;

    for (int k0 = 0; k0 < K; k0 += 8) {
        float4 av = *(const float4*)(Aptr + k0);
        float4 bv = make_float4(0.f, 0.f, 0.f, 0.f);
        if (wvalid) bv = *(const float4*)(Wptr + k0);
        __syncthreads();
        As[lc+0][lr] = av.x; As[lc+1][lr] = av.y; As[lc+2][lr] = av.z; As[lc+3][lr] = av.w;
        Bs[lc+0][lr] = bv.x; Bs[lc+1][lr] = bv.y; Bs[lc+2][lr] = bv.z; Bs[lc+3][lr] = bv.w;
        __syncthreads();
        #pragma unroll
        for (int k = 0; k < 8; k++) {
            float4 a0 = *(const float4*)&As[k][ty*8];
            float4 a1 = *(const float4*)&As[k][ty*8+4];
            float4 b0 = *(const float4*)&Bs[k][tx*8];
            float4 b1 = *(const float4*)&Bs[k][tx*8+4];
            float ar[8] = {a0.x,a0.y,a0.z,a0.w,a1.x,a1.y,a1.z,a1.w};
            float br[8] = {b0.x,b0.y,b0.z,b0.w,b1.x,b1.y,b1.z,b1.w};
            #pragma unroll
            for (int i = 0; i < 8; i++)
                #pragma unroll
                for (int j = 0; j < 8; j++)
                    acc[i][j] = fmaf(ar[i], br[j], acc[i][j]);
        }
    }

    #pragma unroll
    for (int i = 0; i < 8; i++) {
        int m = m0 + ty*8 + i;
        #pragma unroll
        for (int j = 0; j < 8; j++) {
            int n = n0 + tx*8 + j;
            if (n < N) {
                float v = acc[i][j];
                if (ep == 1) {
                    v += bias[n];
                    v = (v > 20.f) ? v : log1pf(expf(v));
                }
                C[(size_t)m*N + n] = v;
            }
        }
    }
}

__global__ void conv_silu_kernel(const float* __restrict__ xr,
                                 const float* __restrict__ cw,
                                 const float* __restrict__ cb,
                                 float* __restrict__ u)
{
    int idx = blockIdx.x*blockDim.x + threadIdx.x;
    if (idx >= ROWS*DI) return;
    int d = idx % DI;
    int row = idx / DI;
    int t = row % L_;
    float acc = cb[d];
    #pragma unroll
    for (int j = 0; j < 4; ++j) {
        int tt = t - 3 + j;
        if (tt >= 0)
            acc = fmaf(cw[d*4 + j], xr[(size_t)(row - 3 + j)*(2*DI) + d], acc);
    }
    u[idx] = acc / (1.f + __expf(-acc));
}

__global__ void scan_kernel(const float* __restrict__ delta,
                            const float* __restrict__ u,
                            const float* __restrict__ xdbl,
                            const float* __restrict__ alog,
                            float* __restrict__ y)
{
    int gid = blockIdx.x*blockDim.x + threadIdx.x;
    int ch = gid >> 4;
    if (ch >= B_*DI) return;
    int n = gid & 15;
    int b = ch / DI, d = ch % DI;
    float An = -__expf(alog[d*DS + n]);
    float state = 0.f;
    const float* drow = delta + (size_t)b*L_*DI + d;
    const float* urow = u     + (size_t)b*L_*DI + d;
    const float* xrow = xdbl  + (size_t)b*L_*80 + DTR + n;
    float* yrow = y + (size_t)b*L_*DI + d;
    for (int t = 0; t < L_; ++t) {
        float dt = drow[(size_t)t*DI];
        float uu = urow[(size_t)t*DI];
        float Bn = xrow[(size_t)t*80];
        float Cn = xrow[(size_t)t*80 + DS];
        float dA = __expf(dt * An);
        state = fmaf(dA, state, dt * Bn * uu);
        float p = state * Cn;
        p += __shfl_xor_sync(0xffffffffu, p, 8);
        p += __shfl_xor_sync(0xffffffffu, p, 4);
        p += __shfl_xor_sync(0xffffffffu, p, 2);
        p += __shfl_xor_sync(0xffffffffu, p, 1);
        if (n == 0) yrow[(size_t)t*DI] = p;
    }
}

__global__ void gate_kernel(float* __restrict__ y,
                            const float* __restrict__ u,
                            const float* __restrict__ Dv,
                            const float* __restrict__ xr)
{
    int idx = blockIdx.x*blockDim.x + threadIdx.x;
    if (idx >= ROWS*DI) return;
    int d = idx % DI;
    int row = idx / DI;
    float r = xr[(size_t)row*(2*DI) + DI + d];
    float g = r / (1.f + __expf(-r));
    y[idx] = (y[idx] + u[idx]*Dv[d]) * g;
}

// ================= launcher =================
static inline void do_split(const float* src, __nv_bfloat16* hi, __nv_bfloat16* lo, size_t n)
{
    int n4 = (int)(n >> 2);
    split_kernel<<<(n4 + 255)/256, 256>>>(src, hi, lo, n4);
}

extern "C" void kernel_launch(void* const* d_in, const int* in_sizes, int n_in,
                              void* d_out, int out_size)
{
    (void)in_sizes; (void)n_in; (void)out_size;
    const int*   ids  = (const int*)d_in[0];
    const float* emb  = (const float*)d_in[2];
    const float* inw  = (const float*)d_in[3];
    const float* cw   = (const float*)d_in[4];
    const float* cb   = (const float*)d_in[5];
    const float* xpw  = (const float*)d_in[6];
    const float* dtw  = (const float*)d_in[7];
    const float* dtb  = (const float*)d_in[8];
    const float* alog = (const float*)d_in[9];
    const float* Dv   = (const float*)d_in[10];
    const float* outw = (const float*)d_in[11];
    const float* nw   = (const float*)d_in[12];
    const float* nfw  = (const float*)d_in[13];
    float* out = (float*)d_out;

    float *x, *xn, *xr, *u, *xdbl, *delta, *y;
    __nv_bfloat16 *ahi, *alo, *whi, *wlo;
    cudaGetSymbolAddress((void**)&x,     g_x);
    cudaGetSymbolAddress((void**)&xn,    g_xn);
    cudaGetSymbolAddress((void**)&xr,    g_xr);
    cudaGetSymbolAddress((void**)&u,     g_u);
    cudaGetSymbolAddress((void**)&xdbl,  g_xdbl);
    cudaGetSymbolAddress((void**)&delta, g_delta);
    cudaGetSymbolAddress((void**)&y,     g_y);
    cudaGetSymbolAddress((void**)&ahi,   g_ahi);
    cudaGetSymbolAddress((void**)&alo,   g_alo);
    cudaGetSymbolAddress((void**)&whi,   g_whi);
    cudaGetSymbolAddress((void**)&wlo,   g_wlo);

    static bool attr_done = false;
    if (!attr_done) {
        cudaFuncSetAttribute(gemm_bf16, cudaFuncAttributeMaxDynamicSharedMemorySize, SM_BYTES);
        attr_done = true;
    }

    embed_kernel<<<(ROWS*DM + 255)/256, 256>>>(ids, emb, x);

    for (int l = 0; l < 2; ++l) {
        rmsnorm_kernel<<<ROWS, 256>>>(x, nw + l*DM, xn);
        // in_proj: [2048,768] @ [3072,768]^T -> xr [2048,3072]
        do_split(xn, ahi, alo, (size_t)ROWS*DM);
        do_split(inw + (size_t)l*2*DI*DM, whi, wlo, (size_t)2*DI*DM);
        gemm_bf16<<<dim3(ROWS/128, (2*DI + 127)/128), 256, SM_BYTES>>>(
            ahi, alo, DM, whi, wlo, 2*DI, xr, 0, nullptr);
        conv_silu_kernel<<<(ROWS*DI + 255)/256, 256>>>(xr, cw + l*DI*4, cb + l*DI, u);
        // x_dbl = u @ x_proj^T : [2048, 80]  (tensorized)
        do_split(u, ahi, alo, (size_t)ROWS*DI);
        do_split(xpw + (size_t)l*80*DI, whi, wlo, (size_t)80*DI);
        gemm_bf16<<<dim3(ROWS/128, 1), 256, SM_BYTES>>>(
            ahi, alo, DI, whi, wlo, 80, xdbl, 0, nullptr);
        // delta = softplus(x_dbl[:, :48] @ dt_proj^T + dt_b)  (small K, FFMA)
        gemm_nt<<<dim3(DI/128, ROWS/128), 256>>>(
            xdbl, 80, dtw + (size_t)l*DI*DTR, delta, DI, DTR, 1, dtb + l*DI);
        scan_kernel<<<(B_*DI*16)/256, 256>>>(delta, u, xdbl, alog + l*DI*DS, y);
        gate_kernel<<<(ROWS*DI + 255)/256, 256>>>(y, u, Dv + l*DI, xr);
        // out_proj: [2048,1536] @ [768,1536]^T + x -> x
        do_split(y, ahi, alo, (size_t)ROWS*DI);
        do_split(outw + (size_t)l*DM*DI, whi, wlo, (size_t)DM*DI);
        gemm_bf16<<<dim3(ROWS/128, (DM + 127)/128), 256, SM_BYTES>>>(
            ahi, alo, DI, whi, wlo, DM, x, 2, x);
    }

    rmsnorm_kernel<<<ROWS, 256>>>(x, nfw, xn);
    // logits: [2048,768] @ [50264,768]^T -> out [2048,50264]
    do_split(xn, ahi, alo, (size_t)ROWS*DM);
    do_split(emb, whi, wlo, (size_t)VOCAB_*DM);
    gemm_bf16<<<dim3(ROWS/128, (VOCAB_ + 127)/128), 256, SM_BYTES>>>(
        ahi, alo, DM, whi, wlo, VOCAB_, out, 0, nullptr);
}